// round 1
// baseline (speedup 1.0000x reference)
#include <cuda_runtime.h>
#include <cstdint>

// Problem constants (fixed by setup_inputs)
#define NUM_T 8192
#define DIM_D 1024
#define DIM_H 512
#define NUM_E 8
#define TPE   1024          // tokens per expert

#define BM  128
#define BK  32
#define BKP 36              // padded smem row stride (floats) -> conflict-free frags
#define SMEM_BYTES (2 * (BM * BKP + BM * BKP) * 4)   // 73728 B (A + B, double buffered)

// Scratch (module-static device memory; no runtime allocation)
__device__ float g_x[(size_t)NUM_T * DIM_D];   // dequantized + tf32-rounded activations
__device__ float g_h[(size_t)NUM_T * DIM_H];   // SwiGLU output (tf32-rounded)

__device__ __forceinline__ uint32_t f2tf(float f) {
    uint32_t r;
    asm("cvt.rna.tf32.f32 %0, %1;" : "=r"(r) : "f"(f));
    return r;
}

#define CP16(dst_u32, src_ptr) \
    asm volatile("cp.async.cg.shared.global [%0], [%1], 16;\n" :: "r"(dst_u32), "l"(src_ptr))
#define CPCOMMIT() asm volatile("cp.async.commit_group;\n")
#define CPWAIT(n)  asm volatile("cp.async.wait_group %0;\n" :: "n"(n))

__device__ __forceinline__ void mma_tf32(float* d, const uint32_t* a, uint32_t b0, uint32_t b1) {
    asm volatile(
        "mma.sync.aligned.m16n8k8.row.col.f32.tf32.tf32.f32 "
        "{%0,%1,%2,%3},{%4,%5,%6,%7},{%8,%9},{%0,%1,%2,%3};\n"
        : "+f"(d[0]), "+f"(d[1]), "+f"(d[2]), "+f"(d[3])
        : "r"(a[0]), "r"(a[1]), "r"(a[2]), "r"(a[3]), "r"(b0), "r"(b1));
}

// ----------------------------------------------------------------------------
// Kernel 0: dequant x = e4m3 * repeat(scales, 32), round-to-nearest tf32
// ----------------------------------------------------------------------------
__global__ void dequant_kernel(const float* __restrict__ xin, const float* __restrict__ sc) {
    int idx = blockIdx.x * 256 + threadIdx.x;          // over T*D/4 float4s
    float4 v = reinterpret_cast<const float4*>(xin)[idx];
    int t  = idx >> 8;                                  // D/4 = 256 float4s per row
    int c4 = idx & 255;                                 // float4 index within row
    float s = __ldg(&sc[t * (DIM_D / 32) + (c4 >> 3)]); // 8 float4s per 32-wide block
    uint4 o;
    o.x = f2tf(v.x * s);
    o.y = f2tf(v.y * s);
    o.z = f2tf(v.z * s);
    o.w = f2tf(v.w * s);
    reinterpret_cast<uint4*>(g_x)[idx] = o;
}

// ----------------------------------------------------------------------------
// Kernel 1: per expert, h = silu(x @ w1^T) * (x @ w3^T), fused epilogue.
// Block computes a 128x64 tile of h; smem B holds 64 w1-rows + 64 w3-rows.
// ----------------------------------------------------------------------------
__global__ __launch_bounds__(256) void gemm1_kernel(const float* __restrict__ w13) {
    extern __shared__ float smem[];
    float* sA = smem;                       // [2][128][36]
    float* sB = smem + 2 * BM * BKP;        // [2][128][36]

    const int e    = blockIdx.z;
    const int m0   = blockIdx.x * BM;       // token tile within expert
    const int n0   = blockIdx.y * 64;       // h column tile (0..511)
    const int tid  = threadIdx.x;
    const int lane = tid & 31;
    const int warp = tid >> 5;
    const int wm   = warp >> 1;             // 0..3
    const int wn   = warp & 1;              // 0..1

    const float* Ag  = g_x + (size_t)(e * TPE + m0) * DIM_D;
    const float* B1g = w13 + (size_t)e * 2 * DIM_H * DIM_D + (size_t)n0 * DIM_D;
    const float* B3g = B1g + (size_t)DIM_H * DIM_D;

    uint32_t sA_u = (uint32_t)__cvta_generic_to_shared(sA);
    uint32_t sB_u = (uint32_t)__cvta_generic_to_shared(sB);

    float acc[2][2][4][4];                  // [side(h1/h3)][mfrag][nfrag][4]
    #pragma unroll
    for (int s = 0; s < 2; s++)
        #pragma unroll
        for (int mf = 0; mf < 2; mf++)
            #pragma unroll
            for (int nf = 0; nf < 4; nf++)
                #pragma unroll
                for (int i = 0; i < 4; i++) acc[s][mf][nf][i] = 0.f;

    auto load_tiles = [&](int kt, int buf) {
        #pragma unroll
        for (int i = 0; i < 4; i++) {
            int id  = tid + i * 256;        // 1024 16B chunks per operand
            int row = id >> 3;
            int ch  = id & 7;
            CP16(sA_u + (uint32_t)((buf * BM * BKP + row * BKP + ch * 4) * 4),
                 Ag + (size_t)row * DIM_D + kt * BK + ch * 4);
            const float* bs = (row < 64) ? (B1g + (size_t)row * DIM_D)
                                         : (B3g + (size_t)(row - 64) * DIM_D);
            CP16(sB_u + (uint32_t)((buf * BM * BKP + row * BKP + ch * 4) * 4),
                 bs + kt * BK + ch * 4);
        }
    };

    load_tiles(0, 0);
    CPCOMMIT();
    int buf = 0;
    const int NK = DIM_D / BK;              // 32
    for (int kt = 0; kt < NK; ++kt) {
        if (kt + 1 < NK) { load_tiles(kt + 1, buf ^ 1); CPCOMMIT(); CPWAIT(1); }
        else             { CPWAIT(0); }
        __syncthreads();

        const float* A = sA + buf * BM * BKP + (wm * 32) * BKP;
        const float* B = sB + buf * BM * BKP;
        #pragma unroll
        for (int k8 = 0; k8 < 4; k8++) {
            const int kc = k8 * 8 + (lane & 3);
            uint32_t a[2][4];
            #pragma unroll
            for (int mf = 0; mf < 2; mf++) {
                int r = mf * 16 + (lane >> 2);
                a[mf][0] = __float_as_uint(A[r * BKP + kc]);          // already tf32-rounded
                a[mf][1] = __float_as_uint(A[(r + 8) * BKP + kc]);
                a[mf][2] = __float_as_uint(A[r * BKP + kc + 4]);
                a[mf][3] = __float_as_uint(A[(r + 8) * BKP + kc + 4]);
            }
            #pragma unroll
            for (int s = 0; s < 2; s++) {
                #pragma unroll
                for (int nf = 0; nf < 4; nf++) {
                    int br = s * 64 + wn * 32 + nf * 8 + (lane >> 2);
                    uint32_t b0 = f2tf(B[br * BKP + kc]);
                    uint32_t b1 = f2tf(B[br * BKP + kc + 4]);
                    mma_tf32(acc[s][0][nf], a[0], b0, b1);
                    mma_tf32(acc[s][1][nf], a[1], b0, b1);
                }
            }
        }
        __syncthreads();
        buf ^= 1;
    }

    // Epilogue: h = a1 * sigmoid(a1) * a3, tf32-round, store fp32
    const int rowBase = e * TPE + m0 + wm * 32 + (lane >> 2);
    const int colBase = n0 + wn * 32 + (lane & 3) * 2;
    #pragma unroll
    for (int mf = 0; mf < 2; mf++)
        #pragma unroll
        for (int nf = 0; nf < 4; nf++)
            #pragma unroll
            for (int hh = 0; hh < 2; hh++) {
                float a1x = acc[0][mf][nf][hh * 2 + 0];
                float a1y = acc[0][mf][nf][hh * 2 + 1];
                float a3x = acc[1][mf][nf][hh * 2 + 0];
                float a3y = acc[1][mf][nf][hh * 2 + 1];
                float hx = a1x * a3x / (1.f + __expf(-a1x));
                float hy = a1y * a3y / (1.f + __expf(-a1y));
                int row = rowBase + mf * 16 + hh * 8;
                int col = colBase + nf * 8;
                float2 st;
                st.x = __uint_as_float(f2tf(hx));
                st.y = __uint_as_float(f2tf(hy));
                *reinterpret_cast<float2*>(&g_h[(size_t)row * DIM_H + col]) = st;
            }
}

// ----------------------------------------------------------------------------
// Kernel 2: per expert, out = h @ w2[e]^T  (out[t,d] = sum_h h[t,h]*w2[e,d,h])
// Block computes a 128x128 output tile.
// ----------------------------------------------------------------------------
__global__ __launch_bounds__(256) void gemm2_kernel(const float* __restrict__ w2,
                                                    float* __restrict__ out) {
    extern __shared__ float smem[];
    float* sA = smem;
    float* sB = smem + 2 * BM * BKP;

    const int e    = blockIdx.z;
    const int m0   = blockIdx.x * BM;
    const int n0   = blockIdx.y * BM;       // output column tile (d dim)
    const int tid  = threadIdx.x;
    const int lane = tid & 31;
    const int warp = tid >> 5;
    const int wm   = warp >> 1;
    const int wn   = warp & 1;

    const float* Ag = g_h + (size_t)(e * TPE + m0) * DIM_H;
    const float* Bg = w2 + (size_t)e * DIM_D * DIM_H + (size_t)n0 * DIM_H;

    uint32_t sA_u = (uint32_t)__cvta_generic_to_shared(sA);
    uint32_t sB_u = (uint32_t)__cvta_generic_to_shared(sB);

    float acc[2][8][4];                     // [mfrag][nfrag][4], warp tile 32x64
    #pragma unroll
    for (int mf = 0; mf < 2; mf++)
        #pragma unroll
        for (int nf = 0; nf < 8; nf++)
            #pragma unroll
            for (int i = 0; i < 4; i++) acc[mf][nf][i] = 0.f;

    auto load_tiles = [&](int kt, int buf) {
        #pragma unroll
        for (int i = 0; i < 4; i++) {
            int id  = tid + i * 256;
            int row = id >> 3;
            int ch  = id & 7;
            CP16(sA_u + (uint32_t)((buf * BM * BKP + row * BKP + ch * 4) * 4),
                 Ag + (size_t)row * DIM_H + kt * BK + ch * 4);
            CP16(sB_u + (uint32_t)((buf * BM * BKP + row * BKP + ch * 4) * 4),
                 Bg + (size_t)row * DIM_H + kt * BK + ch * 4);
        }
    };

    load_tiles(0, 0);
    CPCOMMIT();
    int buf = 0;
    const int NK = DIM_H / BK;              // 16
    for (int kt = 0; kt < NK; ++kt) {
        if (kt + 1 < NK) { load_tiles(kt + 1, buf ^ 1); CPCOMMIT(); CPWAIT(1); }
        else             { CPWAIT(0); }
        __syncthreads();

        const float* A = sA + buf * BM * BKP + (wm * 32) * BKP;
        const float* B = sB + buf * BM * BKP;
        #pragma unroll
        for (int k8 = 0; k8 < 4; k8++) {
            const int kc = k8 * 8 + (lane & 3);
            uint32_t a[2][4];
            #pragma unroll
            for (int mf = 0; mf < 2; mf++) {
                int r = mf * 16 + (lane >> 2);
                a[mf][0] = __float_as_uint(A[r * BKP + kc]);
                a[mf][1] = __float_as_uint(A[(r + 8) * BKP + kc]);
                a[mf][2] = __float_as_uint(A[r * BKP + kc + 4]);
                a[mf][3] = __float_as_uint(A[(r + 8) * BKP + kc + 4]);
            }
            #pragma unroll
            for (int nf = 0; nf < 8; nf++) {
                int br = wn * 64 + nf * 8 + (lane >> 2);
                uint32_t b0 = f2tf(B[br * BKP + kc]);
                uint32_t b1 = f2tf(B[br * BKP + kc + 4]);
                mma_tf32(acc[0][nf], a[0], b0, b1);
                mma_tf32(acc[1][nf], a[1], b0, b1);
            }
        }
        __syncthreads();
        buf ^= 1;
    }

    const int rowBase = e * TPE + m0 + wm * 32 + (lane >> 2);
    const int colBase = n0 + wn * 64 + (lane & 3) * 2;
    #pragma unroll
    for (int mf = 0; mf < 2; mf++)
        #pragma unroll
        for (int nf = 0; nf < 8; nf++)
            #pragma unroll
            for (int hh = 0; hh < 2; hh++) {
                int row = rowBase + mf * 16 + hh * 8;
                int col = colBase + nf * 8;
                float2 st;
                st.x = acc[mf][nf][hh * 2 + 0];
                st.y = acc[mf][nf][hh * 2 + 1];
                *reinterpret_cast<float2*>(&out[(size_t)row * DIM_D + col]) = st;
            }
}

// ----------------------------------------------------------------------------
// Launch
// ----------------------------------------------------------------------------
extern "C" void kernel_launch(void* const* d_in, const int* in_sizes, int n_in,
                              void* d_out, int out_size) {
    const float* xe  = (const float*)d_in[0];   // output_e4m3 (T, D) fp32
    const float* sc  = (const float*)d_in[1];   // output_scales_e8m0 (T, D/32) fp32
    // d_in[2] num_tokens_per_expert, d_in[3] expert_padded_offsets: constant in this problem
    const float* w13 = (const float*)d_in[4];   // (E, 2H, D)
    const float* w2  = (const float*)d_in[5];   // (E, D, H)
    float* out = (float*)d_out;

    cudaFuncSetAttribute(gemm1_kernel, cudaFuncAttributeMaxDynamicSharedMemorySize, SMEM_BYTES);
    cudaFuncSetAttribute(gemm2_kernel, cudaFuncAttributeMaxDynamicSharedMemorySize, SMEM_BYTES);

    dequant_kernel<<<(NUM_T * DIM_D / 4) / 256, 256>>>(xe, sc);

    dim3 g1(TPE / BM, DIM_H / 64, NUM_E);       // (8, 8, 8)
    gemm1_kernel<<<g1, 256, SMEM_BYTES>>>(w13);

    dim3 g2(TPE / BM, DIM_D / BM, NUM_E);       // (8, 8, 8)
    gemm2_kernel<<<g2, 256, SMEM_BYTES>>>(w2, out);
}

// round 13
// speedup vs baseline: 1.2606x; 1.2606x over previous
#include <cuda_runtime.h>
#include <cstdint>

// Problem constants (fixed by setup_inputs)
#define NUM_T 8192
#define DIM_D 1024
#define DIM_H 512
#define NUM_E 8
#define TPE   1024

// Scratch (static device memory; no runtime allocation)
__device__ float g_x  [(size_t)NUM_T * DIM_D];                 // dequant + tf32-rounded x
__device__ float g_h  [(size_t)NUM_T * DIM_H];                 // SwiGLU output (tf32-rounded)
__device__ float g_w13[(size_t)NUM_E * 2 * DIM_H * DIM_D];     // tf32-rounded w13
__device__ float g_w2 [(size_t)NUM_E * DIM_D * DIM_H];         // tf32-rounded w2

// ---------------------------------------------------------------------------
// Helpers
// ---------------------------------------------------------------------------
__device__ __forceinline__ uint32_t f2tf(float f) {
    uint32_t r;
    asm("cvt.rna.tf32.f32 %0, %1;" : "=r"(r) : "f"(f));
    return r;
}

#define CP16(dst_u32, src_ptr) \
    asm volatile("cp.async.cg.shared.global [%0], [%1], 16;\n" :: "r"(dst_u32), "l"(src_ptr))
#define CPCOMMIT() asm volatile("cp.async.commit_group;\n")
#define CPWAIT(n)  asm volatile("cp.async.wait_group %0;\n" :: "n"(n))

#define LDSM_X4(r0, r1, r2, r3, addr) \
    asm volatile("ldmatrix.sync.aligned.m8n8.x4.shared.b16 {%0,%1,%2,%3}, [%4];" \
        : "=r"(r0), "=r"(r1), "=r"(r2), "=r"(r3) : "r"(addr))

__device__ __forceinline__ void mma_tf32(float* d, const uint32_t* a, uint32_t b0, uint32_t b1) {
    asm volatile(
        "mma.sync.aligned.m16n8k8.row.col.f32.tf32.tf32.f32 "
        "{%0,%1,%2,%3},{%4,%5,%6,%7},{%8,%9},{%0,%1,%2,%3};\n"
        : "+f"(d[0]), "+f"(d[1]), "+f"(d[2]), "+f"(d[3])
        : "r"(a[0]), "r"(a[1]), "r"(a[2]), "r"(a[3]), "r"(b0), "r"(b1));
}

__device__ __forceinline__ uint32_t sw128(uint32_t o) { return o ^ ((o >> 3) & 0x70u); }

// Smem: per buffer 32KB = A tile (128x32 f32, 16KB) | B tile (128x32 f32, 16KB)
#define BUFS     32768u
#define OFF_B    16384u
#define SMEM_REQ (1024 + 2 * 32768)

// ---------------------------------------------------------------------------
// Prepasses
// ---------------------------------------------------------------------------
__global__ void dequant_kernel(const float* __restrict__ xin, const float* __restrict__ sc) {
    int idx = blockIdx.x * 256 + threadIdx.x;          // over T*D/4 float4s
    float4 v = reinterpret_cast<const float4*>(xin)[idx];
    int t  = idx >> 8;
    int c4 = idx & 255;
    float s = __ldg(&sc[t * (DIM_D / 32) + (c4 >> 3)]);
    uint4 o;
    o.x = f2tf(v.x * s); o.y = f2tf(v.y * s); o.z = f2tf(v.z * s); o.w = f2tf(v.w * s);
    reinterpret_cast<uint4*>(g_x)[idx] = o;
}

__global__ void round_w13_kernel(const float* __restrict__ in) {
    int i = blockIdx.x * 256 + threadIdx.x;
    float4 v = reinterpret_cast<const float4*>(in)[i];
    uint4 o; o.x = f2tf(v.x); o.y = f2tf(v.y); o.z = f2tf(v.z); o.w = f2tf(v.w);
    reinterpret_cast<uint4*>(g_w13)[i] = o;
}

__global__ void round_w2_kernel(const float* __restrict__ in) {
    int i = blockIdx.x * 256 + threadIdx.x;
    float4 v = reinterpret_cast<const float4*>(in)[i];
    uint4 o; o.x = f2tf(v.x); o.y = f2tf(v.y); o.z = f2tf(v.z); o.w = f2tf(v.w);
    reinterpret_cast<uint4*>(g_w2)[i] = o;
}

// ---------------------------------------------------------------------------
// GEMM1: per expert, h = silu(x@w1^T) * (x@w3^T).
// CTA 128m x 64h (B tile: 64 w1 rows + 64 w3 rows = 128 N rows). 8 warps as
// 4m x 2n; warp = 32m x (32 h1 + 32 h3). BK=32, cp.async double buffer,
// ldmatrix fragment loads, all operands pre-rounded to tf32.
// ---------------------------------------------------------------------------
__global__ __launch_bounds__(256, 2)
void gemm1_kernel() {
    extern __shared__ char smraw[];
    uint32_t smu = ((uint32_t)__cvta_generic_to_shared(smraw) + 1023u) & ~1023u;
    const int tid  = threadIdx.x;
    const int lane = tid & 31;
    const int warp = tid >> 5;
    const int wm   = warp >> 1;            // 0..3
    const int wn   = warp & 1;             // 0..1
    const int e    = blockIdx.z;
    const int m0   = blockIdx.x * 128;
    const int n0h  = blockIdx.y * 64;

    const float* Ag = g_x + (size_t)(e * TPE + m0) * DIM_D;
    const float* B1 = g_w13 + (size_t)e * 2 * DIM_H * DIM_D + (size_t)n0h * DIM_D;
    const float* B3 = B1 + (size_t)DIM_H * DIM_D;

    const int lrow = tid >> 3, lch = tid & 7;  // 1024 16B chunks per tile, 4/thread

    auto load_tile = [&](int kt, int buf) {
        uint32_t b0 = smu + buf * BUFS;
        #pragma unroll
        for (int i = 0; i < 4; i++) {
            int row = lrow + 32 * i;
            uint32_t so = sw128((uint32_t)(row * 128 + lch * 16));
            CP16(b0 + so, Ag + (size_t)row * DIM_D + kt * 32 + lch * 4);
            const float* bs = (row < 64) ? (B1 + (size_t)row * DIM_D)
                                         : (B3 + (size_t)(row - 64) * DIM_D);
            CP16(b0 + OFF_B + so, bs + kt * 32 + lch * 4);
        }
        CPCOMMIT();
    };

    float acc[8][2][4];                    // [nf (0-3 h1, 4-7 h3)][mf][4]
    #pragma unroll
    for (int n = 0; n < 8; n++)
        #pragma unroll
        for (int m = 0; m < 2; m++)
            #pragma unroll
            for (int i = 0; i < 4; i++) acc[n][m][i] = 0.f;

    // ldmatrix per-lane row/khalf selectors
    const int a_roff = ((lane >> 3) & 1) * 8 + (lane & 7);  // +8 rows for mi 1,3
    const int a_koff = ((lane >> 4) & 1) * 16;              // k+4 for mi 2,3
    const int b_nfsel = (lane >> 4) & 1;                    // second nf for mi 2,3
    const int b_koff  = ((lane >> 3) & 1) * 16;             // k+4 for mi 1,3
    const int b_r     = lane & 7;

    load_tile(0, 0);
    const int NK = DIM_D / 32;             // 32
    for (int kt = 0; kt < NK; kt++) {
        int buf = kt & 1;
        if (kt + 1 < NK) { load_tile(kt + 1, buf ^ 1); CPWAIT(1); }
        else             { CPWAIT(0); }
        __syncthreads();

        uint32_t aA = smu + buf * BUFS;
        uint32_t aB = aA + OFF_B;
        #pragma unroll
        for (int k8 = 0; k8 < 4; k8++) {
            uint32_t af[2][4];
            #pragma unroll
            for (int mf = 0; mf < 2; mf++) {
                int row = wm * 32 + mf * 16 + a_roff;
                LDSM_X4(af[mf][0], af[mf][1], af[mf][2], af[mf][3],
                        aA + sw128((uint32_t)(row * 128 + k8 * 32 + a_koff)));
            }
            #pragma unroll
            for (int nfp = 0; nfp < 4; nfp++) {
                // nf pair {2nfp, 2nfp+1}; rows: nf<4 -> wn*32+nf*8 (h1), else 64+wn*32+(nf-4)*8 (h3)
                int nf  = 2 * nfp + b_nfsel;
                int row = (nf < 4) ? (wn * 32 + nf * 8 + b_r)
                                   : (64 + wn * 32 + (nf - 4) * 8 + b_r);
                uint32_t b0a, b1a, b0b, b1b;
                LDSM_X4(b0a, b1a, b0b, b1b,
                        aB + sw128((uint32_t)(row * 128 + k8 * 32 + b_koff)));
                mma_tf32(acc[2 * nfp + 0][0], af[0], b0a, b1a);
                mma_tf32(acc[2 * nfp + 0][1], af[1], b0a, b1a);
                mma_tf32(acc[2 * nfp + 1][0], af[0], b0b, b1b);
                mma_tf32(acc[2 * nfp + 1][1], af[1], b0b, b1b);
            }
        }
        __syncthreads();
    }

    // Epilogue: pair nf (h1) with nf+4 (h3): h = a1*sigmoid(a1)*a3, tf32-round.
    const int rbase = e * TPE + m0 + wm * 32 + (lane >> 2);
    const int cbase = n0h + wn * 32 + (lane & 3) * 2;
    #pragma unroll
    for (int nf = 0; nf < 4; nf++)
        #pragma unroll
        for (int mf = 0; mf < 2; mf++)
            #pragma unroll
            for (int hh = 0; hh < 2; hh++) {
                float a1x = acc[nf][mf][hh * 2 + 0];
                float a1y = acc[nf][mf][hh * 2 + 1];
                float a3x = acc[nf + 4][mf][hh * 2 + 0];
                float a3y = acc[nf + 4][mf][hh * 2 + 1];
                float hx = a1x * a3x / (1.f + __expf(-a1x));
                float hy = a1y * a3y / (1.f + __expf(-a1y));
                int row = rbase + mf * 16 + hh * 8;
                int col = cbase + nf * 8;
                float2 st;
                st.x = __uint_as_float(f2tf(hx));
                st.y = __uint_as_float(f2tf(hy));
                *reinterpret_cast<float2*>(&g_h[(size_t)row * DIM_H + col]) = st;
            }
}

// ---------------------------------------------------------------------------
// GEMM2: out = h @ w2^T per expert. CTA 128m x 128n, warp 32m x 64n. K=512.
// ---------------------------------------------------------------------------
__global__ __launch_bounds__(256, 2)
void gemm2_kernel(float* __restrict__ out) {
    extern __shared__ char smraw[];
    uint32_t smu = ((uint32_t)__cvta_generic_to_shared(smraw) + 1023u) & ~1023u;
    const int tid  = threadIdx.x;
    const int lane = tid & 31;
    const int warp = tid >> 5;
    const int wm   = warp >> 1;
    const int wn   = warp & 1;
    const int e    = blockIdx.z;
    const int m0   = blockIdx.x * 128;
    const int n0   = blockIdx.y * 128;

    const float* Ag = g_h + (size_t)(e * TPE + m0) * DIM_H;
    const float* Bg = g_w2 + (size_t)e * DIM_D * DIM_H + (size_t)n0 * DIM_H;

    const int lrow = tid >> 3, lch = tid & 7;

    auto load_tile = [&](int kt, int buf) {
        uint32_t b0 = smu + buf * BUFS;
        #pragma unroll
        for (int i = 0; i < 4; i++) {
            int row = lrow + 32 * i;
            uint32_t so = sw128((uint32_t)(row * 128 + lch * 16));
            CP16(b0 + so,         Ag + (size_t)row * DIM_H + kt * 32 + lch * 4);
            CP16(b0 + OFF_B + so, Bg + (size_t)row * DIM_H + kt * 32 + lch * 4);
        }
        CPCOMMIT();
    };

    float acc[8][2][4];
    #pragma unroll
    for (int n = 0; n < 8; n++)
        #pragma unroll
        for (int m = 0; m < 2; m++)
            #pragma unroll
            for (int i = 0; i < 4; i++) acc[n][m][i] = 0.f;

    const int a_roff = ((lane >> 3) & 1) * 8 + (lane & 7);
    const int a_koff = ((lane >> 4) & 1) * 16;
    const int b_nfsel = (lane >> 4) & 1;
    const int b_koff  = ((lane >> 3) & 1) * 16;
    const int b_r     = lane & 7;

    load_tile(0, 0);
    const int NK = DIM_H / 32;             // 16
    for (int kt = 0; kt < NK; kt++) {
        int buf = kt & 1;
        if (kt + 1 < NK) { load_tile(kt + 1, buf ^ 1); CPWAIT(1); }
        else             { CPWAIT(0); }
        __syncthreads();

        uint32_t aA = smu + buf * BUFS;
        uint32_t aB = aA + OFF_B;
        #pragma unroll
        for (int k8 = 0; k8 < 4; k8++) {
            uint32_t af[2][4];
            #pragma unroll
            for (int mf = 0; mf < 2; mf++) {
                int row = wm * 32 + mf * 16 + a_roff;
                LDSM_X4(af[mf][0], af[mf][1], af[mf][2], af[mf][3],
                        aA + sw128((uint32_t)(row * 128 + k8 * 32 + a_koff)));
            }
            #pragma unroll
            for (int nfp = 0; nfp < 4; nfp++) {
                int nf  = 2 * nfp + b_nfsel;
                int row = wn * 64 + nf * 8 + b_r;
                uint32_t b0a, b1a, b0b, b1b;
                LDSM_X4(b0a, b1a, b0b, b1b,
                        aB + sw128((uint32_t)(row * 128 + k8 * 32 + b_koff)));
                mma_tf32(acc[2 * nfp + 0][0], af[0], b0a, b1a);
                mma_tf32(acc[2 * nfp + 0][1], af[1], b0a, b1a);
                mma_tf32(acc[2 * nfp + 1][0], af[0], b0b, b1b);
                mma_tf32(acc[2 * nfp + 1][1], af[1], b0b, b1b);
            }
        }
        __syncthreads();
    }

    const int rbase = e * TPE + m0 + wm * 32 + (lane >> 2);
    const int cbase = n0 + wn * 64 + (lane & 3) * 2;
    #pragma unroll
    for (int nf = 0; nf < 8; nf++)
        #pragma unroll
        for (int mf = 0; mf < 2; mf++)
            #pragma unroll
            for (int hh = 0; hh < 2; hh++) {
                int row = rbase + mf * 16 + hh * 8;
                int col = cbase + nf * 8;
                float2 st;
                st.x = acc[nf][mf][hh * 2 + 0];
                st.y = acc[nf][mf][hh * 2 + 1];
                *reinterpret_cast<float2*>(&out[(size_t)row * DIM_D + col]) = st;
            }
}

// ---------------------------------------------------------------------------
// Launch
// ---------------------------------------------------------------------------
extern "C" void kernel_launch(void* const* d_in, const int* in_sizes, int n_in,
                              void* d_out, int out_size) {
    const float* xe  = (const float*)d_in[0];   // output_e4m3 (T, D) fp32
    const float* sc  = (const float*)d_in[1];   // output_scales_e8m0 (T, D/32) fp32
    const float* w13 = (const float*)d_in[4];   // (E, 2H, D)
    const float* w2  = (const float*)d_in[5];   // (E, D, H)
    float* out = (float*)d_out;

    cudaFuncSetAttribute(gemm1_kernel, cudaFuncAttributeMaxDynamicSharedMemorySize, SMEM_REQ);
    cudaFuncSetAttribute(gemm2_kernel, cudaFuncAttributeMaxDynamicSharedMemorySize, SMEM_REQ);

    dequant_kernel <<<(NUM_T * DIM_D / 4) / 256, 256>>>(xe, sc);
    round_w13_kernel<<<(NUM_E * 2 * DIM_H * DIM_D / 4) / 256, 256>>>(w13);
    round_w2_kernel <<<(NUM_E * DIM_D * DIM_H / 4) / 256, 256>>>(w2);

    dim3 g1(TPE / 128, DIM_H / 64, NUM_E);      // (8, 8, 8)
    gemm1_kernel<<<g1, 256, SMEM_REQ>>>();

    dim3 g2(TPE / 128, DIM_D / 128, NUM_E);     // (8, 8, 8)
    gemm2_kernel<<<g2, 256, SMEM_REQ>>>(out);
}

// round 14
// speedup vs baseline: 1.2762x; 1.0124x over previous
#include <cuda_runtime.h>
#include <cstdint>

// Problem constants (fixed by setup_inputs)
#define NUM_T 8192
#define DIM_D 1024
#define DIM_H 512
#define NUM_E 8
#define TPE   1024

// Scratch (static device memory; no runtime allocation)
__device__ float g_x  [(size_t)NUM_T * DIM_D];                 // dequant + tf32-rounded x
__device__ float g_h  [(size_t)NUM_T * DIM_H];                 // SwiGLU output (tf32-rounded)
__device__ float g_w13[(size_t)NUM_E * 2 * DIM_H * DIM_D];     // tf32-rounded w13
__device__ float g_w2 [(size_t)NUM_E * DIM_D * DIM_H];         // tf32-rounded w2

// ---------------------------------------------------------------------------
// Helpers
// ---------------------------------------------------------------------------
__device__ __forceinline__ uint32_t f2tf(float f) {
    uint32_t r;
    asm("cvt.rna.tf32.f32 %0, %1;" : "=r"(r) : "f"(f));
    return r;
}

#define CP16(dst_u32, src_ptr) \
    asm volatile("cp.async.cg.shared.global [%0], [%1], 16;\n" :: "r"(dst_u32), "l"(src_ptr))
#define CPCOMMIT() asm volatile("cp.async.commit_group;\n")
#define CPWAIT(n)  asm volatile("cp.async.wait_group %0;\n" :: "n"(n))

#define LDSM_X4(r0, r1, r2, r3, addr) \
    asm volatile("ldmatrix.sync.aligned.m8n8.x4.shared.b16 {%0,%1,%2,%3}, [%4];" \
        : "=r"(r0), "=r"(r1), "=r"(r2), "=r"(r3) : "r"(addr))

__device__ __forceinline__ void mma_tf32(float* d, const uint32_t* a, uint32_t b0, uint32_t b1) {
    asm volatile(
        "mma.sync.aligned.m16n8k8.row.col.f32.tf32.tf32.f32 "
        "{%0,%1,%2,%3},{%4,%5,%6,%7},{%8,%9},{%0,%1,%2,%3};\n"
        : "+f"(d[0]), "+f"(d[1]), "+f"(d[2]), "+f"(d[3])
        : "r"(a[0]), "r"(a[1]), "r"(a[2]), "r"(a[3]), "r"(b0), "r"(b1));
}

__device__ __forceinline__ uint32_t sw128(uint32_t o) { return o ^ ((o >> 3) & 0x70u); }

// Smem: 3-stage pipeline; per buffer 32KB = A tile (128x32 f32) | B tile (128x32 f32)
#define BUFS     32768u
#define OFF_B    16384u
#define NSTAGE   3
#define SMEM_REQ (1024 + NSTAGE * 32768)

// ---------------------------------------------------------------------------
// Fused prepass: dequant+round x | round w13 | round w2 (one launch)
// ---------------------------------------------------------------------------
#define N4_X   (NUM_T * DIM_D / 4)                       // 2097152
#define N4_W13 (NUM_E * 2 * DIM_H * DIM_D / 4)           // 2097152
#define N4_W2  (NUM_E * DIM_D * DIM_H / 4)               // 1048576
#define N4_ALL (N4_X + N4_W13 + N4_W2)

__global__ void prep_kernel(const float* __restrict__ xin, const float* __restrict__ sc,
                            const float* __restrict__ w13, const float* __restrict__ w2) {
    int idx = blockIdx.x * 256 + threadIdx.x;
    if (idx < N4_X) {
        float4 v = reinterpret_cast<const float4*>(xin)[idx];
        int t  = idx >> 8;                 // D/4 = 256 float4s per row
        int c4 = idx & 255;
        float s = __ldg(&sc[t * (DIM_D / 32) + (c4 >> 3)]);
        uint4 o;
        o.x = f2tf(v.x * s); o.y = f2tf(v.y * s); o.z = f2tf(v.z * s); o.w = f2tf(v.w * s);
        reinterpret_cast<uint4*>(g_x)[idx] = o;
    } else if (idx < N4_X + N4_W13) {
        int i = idx - N4_X;
        float4 v = reinterpret_cast<const float4*>(w13)[i];
        uint4 o; o.x = f2tf(v.x); o.y = f2tf(v.y); o.z = f2tf(v.z); o.w = f2tf(v.w);
        reinterpret_cast<uint4*>(g_w13)[i] = o;
    } else {
        int i = idx - N4_X - N4_W13;
        float4 v = reinterpret_cast<const float4*>(w2)[i];
        uint4 o; o.x = f2tf(v.x); o.y = f2tf(v.y); o.z = f2tf(v.z); o.w = f2tf(v.w);
        reinterpret_cast<uint4*>(g_w2)[i] = o;
    }
}

// ---------------------------------------------------------------------------
// GEMM1: per expert, h = silu(x@w1^T) * (x@w3^T).
// CTA 128m x 64h (B tile: 64 w1 rows + 64 w3 rows). 8 warps as 4m x 2n.
// BK=32, 3-stage cp.async pipeline, ldmatrix fragment loads, tf32 pre-rounded.
// ---------------------------------------------------------------------------
__global__ __launch_bounds__(256, 2)
void gemm1_kernel() {
    extern __shared__ char smraw[];
    uint32_t smu = ((uint32_t)__cvta_generic_to_shared(smraw) + 1023u) & ~1023u;
    const int tid  = threadIdx.x;
    const int lane = tid & 31;
    const int warp = tid >> 5;
    const int wm   = warp >> 1;            // 0..3
    const int wn   = warp & 1;             // 0..1
    const int e    = blockIdx.z;
    const int m0   = blockIdx.x * 128;
    const int n0h  = blockIdx.y * 64;

    const float* Ag = g_x + (size_t)(e * TPE + m0) * DIM_D;
    const float* B1 = g_w13 + (size_t)e * 2 * DIM_H * DIM_D + (size_t)n0h * DIM_D;
    const float* B3 = B1 + (size_t)DIM_H * DIM_D;

    const int lrow = tid >> 3, lch = tid & 7;

    auto load_tile = [&](int kt, int buf) {
        uint32_t b0 = smu + buf * BUFS;
        #pragma unroll
        for (int i = 0; i < 4; i++) {
            int row = lrow + 32 * i;
            uint32_t so = sw128((uint32_t)(row * 128 + lch * 16));
            CP16(b0 + so, Ag + (size_t)row * DIM_D + kt * 32 + lch * 4);
            const float* bs = (row < 64) ? (B1 + (size_t)row * DIM_D)
                                         : (B3 + (size_t)(row - 64) * DIM_D);
            CP16(b0 + OFF_B + so, bs + kt * 32 + lch * 4);
        }
        CPCOMMIT();
    };

    float acc[8][2][4];                    // [nf (0-3 h1, 4-7 h3)][mf][4]
    #pragma unroll
    for (int n = 0; n < 8; n++)
        #pragma unroll
        for (int m = 0; m < 2; m++)
            #pragma unroll
            for (int i = 0; i < 4; i++) acc[n][m][i] = 0.f;

    const int a_roff = ((lane >> 3) & 1) * 8 + (lane & 7);
    const int a_koff = ((lane >> 4) & 1) * 16;
    const int b_nfsel = (lane >> 4) & 1;
    const int b_koff  = ((lane >> 3) & 1) * 16;
    const int b_r     = lane & 7;

    load_tile(0, 0);
    load_tile(1, 1);
    const int NK = DIM_D / 32;             // 32
    int buf = 0;
    for (int kt = 0; kt < NK; kt++) {
        if (kt + 1 < NK) { CPWAIT(1); } else { CPWAIT(0); }
        __syncthreads();
        if (kt + 2 < NK) load_tile(kt + 2, (buf + 2) % NSTAGE);

        uint32_t aA = smu + buf * BUFS;
        uint32_t aB = aA + OFF_B;
        #pragma unroll
        for (int k8 = 0; k8 < 4; k8++) {
            uint32_t af[2][4];
            #pragma unroll
            for (int mf = 0; mf < 2; mf++) {
                int row = wm * 32 + mf * 16 + a_roff;
                LDSM_X4(af[mf][0], af[mf][1], af[mf][2], af[mf][3],
                        aA + sw128((uint32_t)(row * 128 + k8 * 32 + a_koff)));
            }
            #pragma unroll
            for (int nfp = 0; nfp < 4; nfp++) {
                int nf  = 2 * nfp + b_nfsel;
                int row = (nf < 4) ? (wn * 32 + nf * 8 + b_r)
                                   : (64 + wn * 32 + (nf - 4) * 8 + b_r);
                uint32_t b0a, b1a, b0b, b1b;
                LDSM_X4(b0a, b1a, b0b, b1b,
                        aB + sw128((uint32_t)(row * 128 + k8 * 32 + b_koff)));
                mma_tf32(acc[2 * nfp + 0][0], af[0], b0a, b1a);
                mma_tf32(acc[2 * nfp + 0][1], af[1], b0a, b1a);
                mma_tf32(acc[2 * nfp + 1][0], af[0], b0b, b1b);
                mma_tf32(acc[2 * nfp + 1][1], af[1], b0b, b1b);
            }
        }
        buf = (buf + 1) % NSTAGE;
        __syncthreads();
    }

    // Epilogue: h = a1*sigmoid(a1)*a3, tf32-round, store.
    const int rbase = e * TPE + m0 + wm * 32 + (lane >> 2);
    const int cbase = n0h + wn * 32 + (lane & 3) * 2;
    #pragma unroll
    for (int nf = 0; nf < 4; nf++)
        #pragma unroll
        for (int mf = 0; mf < 2; mf++)
            #pragma unroll
            for (int hh = 0; hh < 2; hh++) {
                float a1x = acc[nf][mf][hh * 2 + 0];
                float a1y = acc[nf][mf][hh * 2 + 1];
                float a3x = acc[nf + 4][mf][hh * 2 + 0];
                float a3y = acc[nf + 4][mf][hh * 2 + 1];
                float hx = a1x * a3x / (1.f + __expf(-a1x));
                float hy = a1y * a3y / (1.f + __expf(-a1y));
                int row = rbase + mf * 16 + hh * 8;
                int col = cbase + nf * 8;
                float2 st;
                st.x = __uint_as_float(f2tf(hx));
                st.y = __uint_as_float(f2tf(hy));
                *reinterpret_cast<float2*>(&g_h[(size_t)row * DIM_H + col]) = st;
            }
}

// ---------------------------------------------------------------------------
// GEMM2: out = h @ w2^T per expert. CTA 128m x 128n, warp 32m x 64n. K=512.
// ---------------------------------------------------------------------------
__global__ __launch_bounds__(256, 2)
void gemm2_kernel(float* __restrict__ out) {
    extern __shared__ char smraw[];
    uint32_t smu = ((uint32_t)__cvta_generic_to_shared(smraw) + 1023u) & ~1023u;
    const int tid  = threadIdx.x;
    const int lane = tid & 31;
    const int warp = tid >> 5;
    const int wm   = warp >> 1;
    const int wn   = warp & 1;
    const int e    = blockIdx.z;
    const int m0   = blockIdx.x * 128;
    const int n0   = blockIdx.y * 128;

    const float* Ag = g_h + (size_t)(e * TPE + m0) * DIM_H;
    const float* Bg = g_w2 + (size_t)e * DIM_D * DIM_H + (size_t)n0 * DIM_H;

    const int lrow = tid >> 3, lch = tid & 7;

    auto load_tile = [&](int kt, int buf) {
        uint32_t b0 = smu + buf * BUFS;
        #pragma unroll
        for (int i = 0; i < 4; i++) {
            int row = lrow + 32 * i;
            uint32_t so = sw128((uint32_t)(row * 128 + lch * 16));
            CP16(b0 + so,         Ag + (size_t)row * DIM_H + kt * 32 + lch * 4);
            CP16(b0 + OFF_B + so, Bg + (size_t)row * DIM_H + kt * 32 + lch * 4);
        }
        CPCOMMIT();
    };

    float acc[8][2][4];
    #pragma unroll
    for (int n = 0; n < 8; n++)
        #pragma unroll
        for (int m = 0; m < 2; m++)
            #pragma unroll
            for (int i = 0; i < 4; i++) acc[n][m][i] = 0.f;

    const int a_roff = ((lane >> 3) & 1) * 8 + (lane & 7);
    const int a_koff = ((lane >> 4) & 1) * 16;
    const int b_nfsel = (lane >> 4) & 1;
    const int b_koff  = ((lane >> 3) & 1) * 16;
    const int b_r     = lane & 7;

    load_tile(0, 0);
    load_tile(1, 1);
    const int NK = DIM_H / 32;             // 16
    int buf = 0;
    for (int kt = 0; kt < NK; kt++) {
        if (kt + 1 < NK) { CPWAIT(1); } else { CPWAIT(0); }
        __syncthreads();
        if (kt + 2 < NK) load_tile(kt + 2, (buf + 2) % NSTAGE);

        uint32_t aA = smu + buf * BUFS;
        uint32_t aB = aA + OFF_B;
        #pragma unroll
        for (int k8 = 0; k8 < 4; k8++) {
            uint32_t af[2][4];
            #pragma unroll
            for (int mf = 0; mf < 2; mf++) {
                int row = wm * 32 + mf * 16 + a_roff;
                LDSM_X4(af[mf][0], af[mf][1], af[mf][2], af[mf][3],
                        aA + sw128((uint32_t)(row * 128 + k8 * 32 + a_koff)));
            }
            #pragma unroll
            for (int nfp = 0; nfp < 4; nfp++) {
                int nf  = 2 * nfp + b_nfsel;
                int row = wn * 64 + nf * 8 + b_r;
                uint32_t b0a, b1a, b0b, b1b;
                LDSM_X4(b0a, b1a, b0b, b1b,
                        aB + sw128((uint32_t)(row * 128 + k8 * 32 + b_koff)));
                mma_tf32(acc[2 * nfp + 0][0], af[0], b0a, b1a);
                mma_tf32(acc[2 * nfp + 0][1], af[1], b0a, b1a);
                mma_tf32(acc[2 * nfp + 1][0], af[0], b0b, b1b);
                mma_tf32(acc[2 * nfp + 1][1], af[1], b0b, b1b);
            }
        }
        buf = (buf + 1) % NSTAGE;
        __syncthreads();
    }

    const int rbase = e * TPE + m0 + wm * 32 + (lane >> 2);
    const int cbase = n0 + wn * 64 + (lane & 3) * 2;
    #pragma unroll
    for (int nf = 0; nf < 8; nf++)
        #pragma unroll
        for (int mf = 0; mf < 2; mf++)
            #pragma unroll
            for (int hh = 0; hh < 2; hh++) {
                int row = rbase + mf * 16 + hh * 8;
                int col = cbase + nf * 8;
                float2 st;
                st.x = acc[nf][mf][hh * 2 + 0];
                st.y = acc[nf][mf][hh * 2 + 1];
                *reinterpret_cast<float2*>(&out[(size_t)row * DIM_D + col]) = st;
            }
}

// ---------------------------------------------------------------------------
// Launch
// ---------------------------------------------------------------------------
extern "C" void kernel_launch(void* const* d_in, const int* in_sizes, int n_in,
                              void* d_out, int out_size) {
    const float* xe  = (const float*)d_in[0];   // output_e4m3 (T, D) fp32
    const float* sc  = (const float*)d_in[1];   // output_scales_e8m0 (T, D/32) fp32
    const float* w13 = (const float*)d_in[4];   // (E, 2H, D)
    const float* w2  = (const float*)d_in[5];   // (E, D, H)
    float* out = (float*)d_out;

    cudaFuncSetAttribute(gemm1_kernel, cudaFuncAttributeMaxDynamicSharedMemorySize, SMEM_REQ);
    cudaFuncSetAttribute(gemm2_kernel, cudaFuncAttributeMaxDynamicSharedMemorySize, SMEM_REQ);

    prep_kernel<<<N4_ALL / 256, 256>>>(xe, sc, w13, w2);

    dim3 g1(TPE / 128, DIM_H / 64, NUM_E);      // (8, 8, 8)
    gemm1_kernel<<<g1, 256, SMEM_REQ>>>();

    dim3 g2(TPE / 128, DIM_D / 128, NUM_E);     // (8, 8, 8)
    gemm2_kernel<<<g2, 256, SMEM_REQ>>>(out);
}